// round 3
// baseline (speedup 1.0000x reference)
#include <cuda_runtime.h>
#include <cuda_bf16.h>

// Spatially-varying 19x19 blur.
// out[b,c,i,j] = (1/361) * sum_{u,v} x_reflectpad[b,c,i+u-9,j+v-9] * kernel[b,u*19+v,i,j]
//
// B=2, C=3, H=W=256, L=19, K2=361. Kernel tensor (189 MB) read exactly once.
// R3: 2-way split of the tap (u) reduction -> 8192 warps (~86% occ) to hide DRAM latency.

#define LK    19
#define PADR  9
#define HGT   256
#define WID   256
#define HW    (HGT * WID)
#define K2    (LK * LK)

#define TJ    32      // tile width  (pixels) == warp width
#define TI    8       // tile height (pixels)
#define HALF  (TJ * TI)          // 256 threads per reduction half
#define NTHR  (2 * HALF)         // 512 threads
#define PCOLS (TJ + LK - 1)      // 50
#define PROWS (TI + LK - 1)      // 26
#define U_SPLIT 10               // h=0: u in [0,10), h=1: u in [10,19)

__global__ __launch_bounds__(NTHR)
void svblur_kernel(const float* __restrict__ x,
                   const float* __restrict__ kern,
                   float* __restrict__ out)
{
    __shared__ float sm[3][PROWS][PCOLS];        // 15600 B
    __shared__ float part[HALF][3];              // 3072 B partials from half 1

    const int tid = threadIdx.x;
    const int jt  = blockIdx.x;   // 0..7
    const int it  = blockIdx.y;   // 0..31
    const int b   = blockIdx.z;   // 0..1

    const int j0 = jt * TJ;
    const int i0 = it * TI;

    // ---- stage input patch (reflect padding) into smem, all 3 channels ----
    const float* xb = x + (size_t)b * 3 * HW;
    for (int e = tid; e < PROWS * PCOLS; e += NTHR) {
        int pr = e / PCOLS;
        int pc = e - pr * PCOLS;
        int gi = i0 - PADR + pr;
        int gj = j0 - PADR + pc;
        gi = (gi < 0) ? -gi : ((gi >= HGT) ? 2 * (HGT - 1) - gi : gi);
        gj = (gj < 0) ? -gj : ((gj >= WID) ? 2 * (WID - 1) - gj : gj);
        const float* src = xb + gi * WID + gj;
        sm[0][pr][pc] = src[0 * HW];
        sm[1][pr][pc] = src[1 * HW];
        sm[2][pr][pc] = src[2 * HW];
    }
    __syncthreads();

    const int h    = tid >> 8;            // reduction half: 0 or 1
    const int tid2 = tid & (HALF - 1);    // 0..255 : pixel id within tile
    const int jl = tid2 & (TJ - 1);       // lane / j within tile
    const int ir = tid2 >> 5;             // row within tile
    const int i  = i0 + ir;
    const int j  = j0 + jl;

    const int u_lo = h ? U_SPLIT : 0;
    const int u_hi = h ? LK : U_SPLIT;

    const float* kp = kern + (size_t)b * K2 * HW + (size_t)i * WID + j;

    float a0 = 0.f, a1 = 0.f, a2 = 0.f;

    #pragma unroll 1
    for (int u = u_lo; u < u_hi; u++) {
        const float* kr = kp + (size_t)u * LK * HW;
        const float* s0 = &sm[0][ir + u][jl];
        const float* s1 = &sm[1][ir + u][jl];
        const float* s2 = &sm[2][ir + u][jl];
        #pragma unroll
        for (int v = 0; v < LK; v++) {
            float kv = __ldg(kr + (size_t)v * HW);
            a0 += s0[v] * kv;
            a1 += s1[v] * kv;
            a2 += s2[v] * kv;
        }
    }

    // ---- combine the two halves ----
    if (h) {
        part[tid2][0] = a0;
        part[tid2][1] = a1;
        part[tid2][2] = a2;
    }
    __syncthreads();
    if (!h) {
        a0 += part[tid2][0];
        a1 += part[tid2][1];
        a2 += part[tid2][2];
        const float inv = 1.0f / (float)K2;
        float* ob = out + (size_t)b * 3 * HW + (size_t)i * WID + j;
        ob[0 * HW] = a0 * inv;
        ob[1 * HW] = a1 * inv;
        ob[2 * HW] = a2 * inv;
    }
}

extern "C" void kernel_launch(void* const* d_in, const int* in_sizes, int n_in,
                              void* d_out, int out_size)
{
    const float* x    = (const float*)d_in[0];
    const float* kern = (const float*)d_in[1];
    // defensive: identify tensors by size (input = 393216, kernel = 47316992)
    if (n_in >= 2 && in_sizes[0] > in_sizes[1]) {
        const float* t = x; x = kern; kern = t;
    }

    dim3 grid(WID / TJ, HGT / TI, 2);   // (8, 32, 2) = 512 blocks, 16 warps each
    svblur_kernel<<<grid, NTHR>>>(x, kern, (float*)d_out);
}

// round 4
// speedup vs baseline: 1.1614x; 1.1614x over previous
#include <cuda_runtime.h>
#include <cuda_bf16.h>

// Spatially-varying 19x19 blur.
// out[b,c,i,j] = (1/361) * sum_{u,v} x_reflectpad[b,c,i+u-9,j+v-9] * kernel[b,u*19+v,i,j]
//
// B=2, C=3, H=W=256, L=19, K2=361. Kernel tensor (189 MB) read exactly once.
// R4: float4 kernel loads -> each warp reads 512B contiguous per tap (DRAM burst
// locality), 4-way tap split keeps 4096 warps. v processed in chunks of 4 with
// two aligned LDS.128 per channel to keep regs ~56 (no spills).

#define LK    19
#define PADR  9
#define HGT   256
#define WID   256
#define HW    (HGT * WID)
#define K2    (LK * LK)

#define TJ    128     // tile width (pixels): 32 j-threads x 4 px
#define TI    2       // tile height (pixels)
#define PGRP  64      // pixel-group threads (32 x 2)
#define NGRP  4       // tap groups
#define NTHR  (PGRP * NGRP)      // 256
#define PCOLS (TJ + LK - 1)      // 146
#define PROWS (TI + LK - 1)      // 20
#define PITCH 148                // 16B-aligned rows, covers col 147 reads

__global__ __launch_bounds__(NTHR, 4)
void svblur_kernel(const float* __restrict__ x,
                   const float* __restrict__ kern,
                   float* __restrict__ out)
{
    __shared__ float sm[3][PROWS][PITCH];     // 35520 B
    __shared__ float part[NGRP - 1][PGRP][13]; // 9984 B (pad 13: conflict-free)

    const int tid = threadIdx.x;
    const int jt  = blockIdx.x;   // 0..1
    const int it  = blockIdx.y;   // 0..127
    const int b   = blockIdx.z;   // 0..1

    const int j0 = jt * TJ;
    const int i0 = it * TI;

    // ---- stage input patch (reflect padding), all 3 channels ----
    const float* xb = x + (size_t)b * 3 * HW;
    for (int e = tid; e < PROWS * PCOLS; e += NTHR) {
        int pr = e / PCOLS;
        int pc = e - pr * PCOLS;
        int gi = i0 - PADR + pr;
        int gj = j0 - PADR + pc;
        gi = (gi < 0) ? -gi : ((gi >= HGT) ? 2 * (HGT - 1) - gi : gi);
        gj = (gj < 0) ? -gj : ((gj >= WID) ? 2 * (WID - 1) - gj : gj);
        const float* src = xb + gi * WID + gj;
        sm[0][pr][pc] = src[0 * HW];
        sm[1][pr][pc] = src[1 * HW];
        sm[2][pr][pc] = src[2 * HW];
    }
    __syncthreads();

    const int g    = tid >> 6;            // tap group 0..3
    const int tid2 = tid & (PGRP - 1);    // 0..63
    const int jthr = tid2 & 31;           // 0..31
    const int ir   = tid2 >> 5;           // 0..1
    const int i    = i0 + ir;
    const int jj   = jthr * 4;            // local j of first of 4 px
    const int j    = j0 + jj;

    const int u_lo = (g * LK) / NGRP;         // 0,4,9,14
    const int u_hi = ((g + 1) * LK) / NGRP;   // 4,9,14,19

    const float4* kp = (const float4*)(kern + (size_t)b * K2 * HW
                                            + (size_t)i * WID + j);

    float a0[4] = {0.f, 0.f, 0.f, 0.f};
    float a1[4] = {0.f, 0.f, 0.f, 0.f};
    float a2[4] = {0.f, 0.f, 0.f, 0.f};

    #pragma unroll 1
    for (int u = u_lo; u < u_hi; u++) {
        const float4* kru = kp + (size_t)u * LK * (HW / 4);
        const float4* r0  = (const float4*)&sm[0][ir + u][0];
        const float4* r1  = (const float4*)&sm[1][ir + u][0];
        const float4* r2  = (const float4*)&sm[2][ir + u][0];
        const int jb = jthr;   // jj/4

        #pragma unroll
        for (int vb = 0; vb < 5; vb++) {          // v chunks: 4,4,4,4,3
            // 8-float windows starting at col jj + 4*vb (16B aligned)
            float4 lo0 = r0[jb + vb], hi0 = r0[jb + vb + 1];
            float4 lo1 = r1[jb + vb], hi1 = r1[jb + vb + 1];
            float4 lo2 = r2[jb + vb], hi2 = r2[jb + vb + 1];
            float w0[8] = {lo0.x, lo0.y, lo0.z, lo0.w, hi0.x, hi0.y, hi0.z, hi0.w};
            float w1[8] = {lo1.x, lo1.y, lo1.z, lo1.w, hi1.x, hi1.y, hi1.z, hi1.w};
            float w2[8] = {lo2.x, lo2.y, lo2.z, lo2.w, hi2.x, hi2.y, hi2.z, hi2.w};

            const int vmax = (vb == 4) ? 3 : 4;
            #pragma unroll
            for (int s = 0; s < 4; s++) {
                if (s >= vmax) break;
                const int v = vb * 4 + s;
                float4 kv = __ldg(kru + (size_t)v * (HW / 4));
                a0[0] += w0[s + 0] * kv.x;  a0[1] += w0[s + 1] * kv.y;
                a0[2] += w0[s + 2] * kv.z;  a0[3] += w0[s + 3] * kv.w;
                a1[0] += w1[s + 0] * kv.x;  a1[1] += w1[s + 1] * kv.y;
                a1[2] += w1[s + 2] * kv.z;  a1[3] += w1[s + 3] * kv.w;
                a2[0] += w2[s + 0] * kv.x;  a2[1] += w2[s + 1] * kv.y;
                a2[2] += w2[s + 2] * kv.z;  a2[3] += w2[s + 3] * kv.w;
            }
        }
    }

    // ---- combine the 4 tap-groups ----
    if (g > 0) {
        float* p = part[g - 1][tid2];
        #pragma unroll
        for (int t = 0; t < 4; t++) { p[t] = a0[t]; p[4 + t] = a1[t]; p[8 + t] = a2[t]; }
    }
    __syncthreads();
    if (g == 0) {
        #pragma unroll
        for (int q = 0; q < NGRP - 1; q++) {
            const float* p = part[q][tid2];
            #pragma unroll
            for (int t = 0; t < 4; t++) {
                a0[t] += p[t]; a1[t] += p[4 + t]; a2[t] += p[8 + t];
            }
        }
        const float inv = 1.0f / (float)K2;
        float* ob = out + (size_t)b * 3 * HW + (size_t)i * WID + j;
        float4 o0 = make_float4(a0[0]*inv, a0[1]*inv, a0[2]*inv, a0[3]*inv);
        float4 o1 = make_float4(a1[0]*inv, a1[1]*inv, a1[2]*inv, a1[3]*inv);
        float4 o2 = make_float4(a2[0]*inv, a2[1]*inv, a2[2]*inv, a2[3]*inv);
        *(float4*)(ob + 0 * HW) = o0;
        *(float4*)(ob + 1 * HW) = o1;
        *(float4*)(ob + 2 * HW) = o2;
    }
}

extern "C" void kernel_launch(void* const* d_in, const int* in_sizes, int n_in,
                              void* d_out, int out_size)
{
    const float* x    = (const float*)d_in[0];
    const float* kern = (const float*)d_in[1];
    // defensive: identify tensors by size (input = 393216, kernel = 47316992)
    if (n_in >= 2 && in_sizes[0] > in_sizes[1]) {
        const float* t = x; x = kern; kern = t;
    }

    dim3 grid(WID / TJ, HGT / TI, 2);   // (2, 128, 2) = 512 blocks
    svblur_kernel<<<grid, NTHR>>>(x, kern, (float*)d_out);
}